// round 14
// baseline (speedup 1.0000x reference)
#include <cuda_runtime.h>
#include <cuda_fp16.h>
#include <cstdint>

using h16 = __half;

#define T_TOK 8192
#define HDIM  2048
#define FDIM  4096
#define NEXP  8
#define BK    64

static const size_t WSZ = (size_t)FDIM * HDIM;

// ---------------- persistent scratch ----------------
__device__ int   g_cnt[NEXP];
__device__ int   g_list[NEXP][T_TOK];
__device__ float g_wt[NEXP][T_TOK];

__device__ h16 g_x[(size_t)T_TOK * HDIM];
__device__ h16 g_act[9 * (size_t)T_TOK * FDIM];

// ---------------- helpers ----------------
__device__ __forceinline__ uint32_t sm_addr(const void* p) {
    return (uint32_t)__cvta_generic_to_shared(p);
}
__device__ __forceinline__ void ldsm_x4(uint32_t* r, const h16* p) {
    uint32_t a = sm_addr(p);
    asm volatile("ldmatrix.sync.aligned.m8n8.x4.shared.b16 {%0,%1,%2,%3}, [%4];\n"
                 : "=r"(r[0]), "=r"(r[1]), "=r"(r[2]), "=r"(r[3]) : "r"(a));
}
__device__ __forceinline__ void mma_f16(float* d, const uint32_t* a, const uint32_t* b) {
    asm volatile(
        "mma.sync.aligned.m16n8k16.row.col.f32.f16.f16.f32 "
        "{%0,%1,%2,%3}, {%4,%5,%6,%7}, {%8,%9}, {%0,%1,%2,%3};\n"
        : "+f"(d[0]), "+f"(d[1]), "+f"(d[2]), "+f"(d[3])
        : "r"(a[0]), "r"(a[1]), "r"(a[2]), "r"(a[3]), "r"(b[0]), "r"(b[1]));
}
__device__ __forceinline__ uint32_t pack2h(h16 a, h16 b) {
    union { __half2 v; uint32_t u; } t;
    t.v = __halves2half2(a, b);
    return t.u;
}
__device__ __forceinline__ void cp16(void* dst, const void* src, bool valid) {
    uint32_t d = sm_addr(dst);
    int sz = valid ? 16 : 0;
    asm volatile("cp.async.cg.shared.global [%0], [%1], 16, %2;\n"
                 :: "r"(d), "l"(src), "r"(sz));
}
#define CP_COMMIT() asm volatile("cp.async.commit_group;\n" ::: "memory")
#define CP_WAIT(n)  asm volatile("cp.async.wait_group %0;\n" :: "n"(n) : "memory")

// ---------------- conversion of x ----------------
__global__ void __launch_bounds__(256) split1_arr(
    const float* __restrict__ src, h16* __restrict__ dst, size_t n4)
{
    size_t i = blockIdx.x * (size_t)blockDim.x + threadIdx.x;
    size_t stride = (size_t)gridDim.x * blockDim.x;
    const float4* s4 = (const float4*)src;
    for (; i < n4; i += stride) {
        float4 v = s4[i];
        *reinterpret_cast<uint2*>(dst + i * 4) = make_uint2(
            pack2h(__float2half_rn(v.x), __float2half_rn(v.y)),
            pack2h(__float2half_rn(v.z), __float2half_rn(v.w)));
    }
}

__global__ void reset_kernel() {
    if (threadIdx.x < NEXP) g_cnt[threadIdx.x] = 0;
}

__global__ void __launch_bounds__(256) zero_out(float4* __restrict__ out, size_t n4)
{
    size_t i = blockIdx.x * (size_t)blockDim.x + threadIdx.x;
    size_t stride = (size_t)gridDim.x * blockDim.x;
    const float4 z = make_float4(0.f, 0.f, 0.f, 0.f);
    for (; i < n4; i += stride) out[i] = z;
}

// ---------------- router: 4 tokens per block ----------------
__global__ void __launch_bounds__(256) router_kernel(
    const float* __restrict__ X, const float* __restrict__ RW,
    const float* __restrict__ RB, float* __restrict__ LOG)
{
    __shared__ float slog[4][NEXP];
    const int tid  = threadIdx.x;
    const int sub  = tid >> 6;
    const int stid = tid & 63;
    const int t    = blockIdx.x * 4 + sub;

    const int w    = stid >> 5;
    const int lane = stid & 31;

    const float* xrow = X + (size_t)t * HDIM;
    #pragma unroll
    for (int eo = 0; eo < 4; eo++) {
        int e = w + eo * 2;
        const float* rw = RW + (size_t)e * HDIM;
        float s = 0.f;
        for (int i = lane; i < HDIM; i += 32) s += xrow[i] * rw[i];
        #pragma unroll
        for (int off = 16; off > 0; off >>= 1) s += __shfl_xor_sync(0xffffffffu, s, off);
        if (lane == 0) slog[sub][e] = s + RB[e];
    }
    __syncthreads();

    if (stid == 0) {
        float l[NEXP];
        float m = -1e30f;
        #pragma unroll
        for (int e = 0; e < NEXP; e++) {
            l[e] = slog[sub][e];
            LOG[(size_t)t * NEXP + e] = l[e];
            m = fmaxf(m, l[e]);
        }
        float p[NEXP];
        #pragma unroll
        for (int e = 0; e < NEXP; e++) p[e] = __expf(l[e] - m);
        int i0 = 0;
        #pragma unroll
        for (int e = 1; e < NEXP; e++) if (l[e] > l[i0]) i0 = e;
        int i1 = -1;
        #pragma unroll
        for (int e = 0; e < NEXP; e++) {
            if (e == i0) continue;
            if (i1 < 0 || l[e] > l[i1]) i1 = e;
        }
        float ws = p[i0] + p[i1];
        float w0 = p[i0] / ws, w1 = p[i1] / ws;
        int p0 = atomicAdd(&g_cnt[i0], 1);
        g_list[i0][p0] = t; g_wt[i0][p0] = w0;
        int p1 = atomicAdd(&g_cnt[i1], 1);
        g_list[i1][p1] = t; g_wt[i1][p1] = w1;
    }
}

// ---------------- smem geometry ----------------
// A (fp16, gathered rows): 128 x 64 halfs @ stride 72 -> 18432 B, 3 stages
// B16 (fp16 ldsm buffer):  256 x 64 halfs @ stride 72 -> 36864 B, 1 buffer
// B32 (fp32 staged weights): 256 rows x 64 fl @ stride 68 -> 69632 B, 2 stages
#define A_ST    72
#define A_BYTES 18432
#define OFF_B16 (3 * A_BYTES)                  // 55296
#define OFF_B32(s) (55296 + 36864 + (s) * 69632)
#define SMEMB   231424

// convert one full B stage (fp32 -> fp16), 512 threads
__device__ __forceinline__ void convert_B(const char* b32, char* b16, int tid)
{
    const int r = tid >> 1;
    const int h = tid & 1;
    const float4* src = reinterpret_cast<const float4*>(b32 + r * 272 + h * 128);
    uint32_t* dst = reinterpret_cast<uint32_t*>(b16 + r * 144 + h * 64);
    #pragma unroll
    for (int i = 0; i < 8; i++) {
        float4 v = src[i];
        dst[2 * i]     = pack2h(__float2half_rn(v.x), __float2half_rn(v.y));
        dst[2 * i + 1] = pack2h(__float2half_rn(v.z), __float2half_rn(v.w));
    }
}

// ---------------- GEMM13: act[z] = silu(X w1^T) * (X w3^T), fp32 weights ----------------
__global__ void __launch_bounds__(512) gemm13_kernel(
    const float* __restrict__ w1, const float* __restrict__ w3,
    const float* __restrict__ sw1, const float* __restrict__ sw3)
{
    const int z = blockIdx.z;
    const int count = (z == NEXP) ? T_TOK : g_cnt[z];
    const int m0 = blockIdx.y * 128;
    if (m0 >= count) return;
    const int n0 = blockIdx.x * 128;

    extern __shared__ __align__(16) char smem[];

    const float* __restrict__ W1f = (z == NEXP) ? sw1 : w1 + (size_t)z * WSZ;
    const float* __restrict__ W3f = (z == NEXP) ? sw3 : w3 + (size_t)z * WSZ;

    const int tid  = threadIdx.x;
    const int lane = tid & 31;
    const int warp = tid >> 5;
    const int wm = (warp & 3) * 32;
    const int wn = (warp >> 2) * 32;

    const int r0  = tid >> 3;            // 0..63
    const int c8  = tid & 7;             // chunk index

    // A gather state
    bool av0 = (m0 + r0) < count;
    bool av1 = (m0 + r0 + 64) < count;
    int tok0 = 0, tok1 = 0;
    if (av0) tok0 = (z == NEXP) ? (m0 + r0)      : g_list[z][m0 + r0];
    if (av1) tok1 = (z == NEXP) ? (m0 + r0 + 64) : g_list[z][m0 + r0 + 64];
    const h16* asrc0 = g_x + (size_t)tok0 * HDIM + c8 * 8;
    const h16* asrc1 = g_x + (size_t)tok1 * HDIM + c8 * 8;
    const int aoff = r0 * A_ST + c8 * 8;   // halfs

    // B fp32 sources: rows r0(+64) of W1 and W3
    const float* bsrc[4] = {
        W1f + (size_t)(n0 + r0)      * HDIM + c8 * 4,
        W1f + (size_t)(n0 + r0 + 64) * HDIM + c8 * 4,
        W3f + (size_t)(n0 + r0)      * HDIM + c8 * 4,
        W3f + (size_t)(n0 + r0 + 64) * HDIM + c8 * 4 };
    int b32off[4];
    #pragma unroll
    for (int j = 0; j < 4; j++) b32off[j] = (64 * j + r0) * 272 + c8 * 16;

    float acc1[2][4][4];
    float acc3[2][4][4];
    #pragma unroll
    for (int i = 0; i < 2; i++)
        #pragma unroll
        for (int j = 0; j < 4; j++)
            #pragma unroll
            for (int q = 0; q < 4; q++) { acc1[i][j][q] = 0.f; acc3[i][j][q] = 0.f; }

    const int a_r = (lane & 7) + ((lane >> 3) & 1) * 8;
    const int a_c = ((lane >> 4) & 1) * 8;
    const int b_r = (lane & 7) + ((lane >> 4) & 1) * 8;
    const int b_c = ((lane >> 3) & 1) * 8;

    const int KT = HDIM / BK;   // 32

    auto load_stage = [&](int s3, int s2, int k0) {
        char* ab = smem + s3 * A_BYTES;
        cp16(ab + aoff * 2,                 asrc0 + k0, av0);
        cp16(ab + (aoff + 64 * A_ST) * 2,   asrc1 + k0, av1);
        char* bb = smem + OFF_B32(s2);
        #pragma unroll
        for (int j = 0; j < 4; j++) {
            cp16(bb + b32off[j],       bsrc[j] + k0, true);
            cp16(bb + b32off[j] + 128, bsrc[j] + k0 + 32, true);
        }
        CP_COMMIT();
    };

    load_stage(0, 0, 0);
    load_stage(1, 1, BK);

    for (int kt = 0; kt < KT; kt++) {
        if (kt + 1 < KT) { CP_WAIT(1); } else { CP_WAIT(0); }
        __syncthreads();
        convert_B(smem + OFF_B32(kt & 1), smem + OFF_B16, tid);
        __syncthreads();
        if (kt + 2 < KT) load_stage((kt + 2) % 3, kt & 1, (kt + 2) * BK);

        const h16* base = reinterpret_cast<const h16*>(smem + (kt % 3) * A_BYTES);
        const h16* bB = reinterpret_cast<const h16*>(smem + OFF_B16);

        #pragma unroll
        for (int kk = 0; kk < BK; kk += 16) {
            uint32_t a[2][4];
            ldsm_x4(a[0], base + (wm +      a_r) * A_ST + kk + a_c);
            ldsm_x4(a[1], base + (wm + 16 + a_r) * A_ST + kk + a_c);
            #pragma unroll
            for (int pb = 0; pb < 2; pb++) {
                uint32_t b1[4], b3[4];
                ldsm_x4(b1, bB + (wn + pb * 16 + b_r) * A_ST + kk + b_c);
                ldsm_x4(b3, bB + (128 + wn + pb * 16 + b_r) * A_ST + kk + b_c);
                #pragma unroll
                for (int mi = 0; mi < 2; mi++) {
                    mma_f16(acc1[mi][pb * 2 + 0], a[mi], &b1[0]);
                    mma_f16(acc1[mi][pb * 2 + 1], a[mi], &b1[2]);
                    mma_f16(acc3[mi][pb * 2 + 0], a[mi], &b3[0]);
                    mma_f16(acc3[mi][pb * 2 + 1], a[mi], &b3[2]);
                }
            }
        }
    }

    h16* actz = g_act + (size_t)z * T_TOK * FDIM;
    #pragma unroll
    for (int mi = 0; mi < 2; mi++) {
        #pragma unroll
        for (int q2 = 0; q2 < 2; q2++) {
            int r_loc = m0 + wm + mi * 16 + (lane >> 2) + q2 * 8;
            if (r_loc >= count) continue;
            h16* arow = actz + (size_t)r_loc * FDIM;
            #pragma unroll
            for (int ni = 0; ni < 4; ni++) {
                int c = n0 + wn + ni * 8 + (lane & 3) * 2;
                float a0 = acc1[mi][ni][q2 * 2 + 0];
                float a1 = acc1[mi][ni][q2 * 2 + 1];
                float b0 = acc3[mi][ni][q2 * 2 + 0];
                float b1 = acc3[mi][ni][q2 * 2 + 1];
                float v0 = (a0 / (1.f + __expf(-a0))) * b0;
                float v1 = (a1 / (1.f + __expf(-a1))) * b1;
                *reinterpret_cast<uint32_t*>(arow + c) =
                    pack2h(__float2half_rn(v0), __float2half_rn(v1));
            }
        }
    }
}

// ---------------- GEMM2 (all passes, atomic): out += w * (act[z] @ w2^T), fp32 weights ----------------
__global__ void __launch_bounds__(512) gemm2_kernel(
    float* __restrict__ OUT,
    const float* __restrict__ w2, const float* __restrict__ sw2)
{
    const int z = blockIdx.z;
    const int count = (z == NEXP) ? T_TOK : g_cnt[z];
    const int m0 = blockIdx.y * 128;
    if (m0 >= count) return;
    const int n0 = blockIdx.x * 256;

    extern __shared__ __align__(16) char smem[];

    const float* __restrict__ W2f = (z == NEXP) ? sw2 : w2 + (size_t)z * WSZ;
    const h16* __restrict__ actz = g_act + (size_t)z * T_TOK * FDIM;

    const int tid  = threadIdx.x;
    const int lane = tid & 31;
    const int warp = tid >> 5;
    const int wm = (warp & 3) * 32;
    const int wn = (warp >> 2) * 64;

    const int r0  = tid >> 3;
    const int c8  = tid & 7;

    const bool av0 = (m0 + r0) < count;
    const bool av1 = (m0 + r0 + 64) < count;
    const h16* asrc0 = actz + (size_t)(av0 ? (m0 + r0)      : 0) * FDIM + c8 * 8;
    const h16* asrc1 = actz + (size_t)(av1 ? (m0 + r0 + 64) : 0) * FDIM + c8 * 8;
    const int aoff = r0 * A_ST + c8 * 8;

    const float* bsrc[4];
    int b32off[4];
    #pragma unroll
    for (int j = 0; j < 4; j++) {
        bsrc[j] = W2f + (size_t)(n0 + r0 + 64 * j) * FDIM + c8 * 4;
        b32off[j] = (64 * j + r0) * 272 + c8 * 16;
    }

    float acc[2][8][4];
    #pragma unroll
    for (int i = 0; i < 2; i++)
        #pragma unroll
        for (int j = 0; j < 8; j++)
            #pragma unroll
            for (int q = 0; q < 4; q++) acc[i][j][q] = 0.f;

    const int a_r = (lane & 7) + ((lane >> 3) & 1) * 8;
    const int a_c = ((lane >> 4) & 1) * 8;
    const int b_r = (lane & 7) + ((lane >> 4) & 1) * 8;
    const int b_c = ((lane >> 3) & 1) * 8;

    const int KT = FDIM / BK;   // 64

    auto load_stage = [&](int s3, int s2, int k0) {
        char* ab = smem + s3 * A_BYTES;
        cp16(ab + aoff * 2,               asrc0 + k0, av0);
        cp16(ab + (aoff + 64 * A_ST) * 2, asrc1 + k0, av1);
        char* bb = smem + OFF_B32(s2);
        #pragma unroll
        for (int j = 0; j < 4; j++) {
            cp16(bb + b32off[j],       bsrc[j] + k0, true);
            cp16(bb + b32off[j] + 128, bsrc[j] + k0 + 32, true);
        }
        CP_COMMIT();
    };

    load_stage(0, 0, 0);
    load_stage(1, 1, BK);

    for (int kt = 0; kt < KT; kt++) {
        if (kt + 1 < KT) { CP_WAIT(1); } else { CP_WAIT(0); }
        __syncthreads();
        convert_B(smem + OFF_B32(kt & 1), smem + OFF_B16, tid);
        __syncthreads();
        if (kt + 2 < KT) load_stage((kt + 2) % 3, kt & 1, (kt + 2) * BK);

        const h16* base = reinterpret_cast<const h16*>(smem + (kt % 3) * A_BYTES);
        const h16* bB = reinterpret_cast<const h16*>(smem + OFF_B16);

        #pragma unroll
        for (int kk = 0; kk < BK; kk += 16) {
            uint32_t a[2][4];
            ldsm_x4(a[0], base + (wm +      a_r) * A_ST + kk + a_c);
            ldsm_x4(a[1], base + (wm + 16 + a_r) * A_ST + kk + a_c);
            #pragma unroll
            for (int pb = 0; pb < 4; pb++) {
                uint32_t b[4];
                ldsm_x4(b, bB + (wn + pb * 16 + b_r) * A_ST + kk + b_c);
                #pragma unroll
                for (int mi = 0; mi < 2; mi++) {
                    mma_f16(acc[mi][pb * 2 + 0], a[mi], &b[0]);
                    mma_f16(acc[mi][pb * 2 + 1], a[mi], &b[2]);
                }
            }
        }
    }

    #pragma unroll
    for (int mi = 0; mi < 2; mi++) {
        #pragma unroll
        for (int q2 = 0; q2 < 2; q2++) {
            int r_loc = m0 + wm + mi * 16 + (lane >> 2) + q2 * 8;
            if (r_loc >= count) continue;
            int tok; float wgt;
            if (z == NEXP) { tok = r_loc; wgt = 1.f; }
            else { tok = g_list[z][r_loc]; wgt = g_wt[z][r_loc]; }
            float* orow = OUT + (size_t)tok * HDIM;
            #pragma unroll
            for (int ni = 0; ni < 8; ni++) {
                #pragma unroll
                for (int q1 = 0; q1 < 2; q1++) {
                    int c = n0 + wn + ni * 8 + (lane & 3) * 2 + q1;
                    atomicAdd(&orow[c], wgt * acc[mi][ni][q2 * 2 + q1]);
                }
            }
        }
    }
}

// ---------------- launch ----------------
extern "C" void kernel_launch(void* const* d_in, const int* in_sizes, int n_in,
                              void* d_out, int out_size)
{
    const float* x   = (const float*)d_in[0];
    const float* rw  = (const float*)d_in[1];
    const float* rb  = (const float*)d_in[2];
    const float* w1  = (const float*)d_in[3];
    const float* w2  = (const float*)d_in[4];
    const float* w3  = (const float*)d_in[5];
    const float* sw1 = (const float*)d_in[6];
    const float* sw2 = (const float*)d_in[7];
    const float* sw3 = (const float*)d_in[8];

    float* out    = (float*)d_out;
    float* logits = out + (size_t)T_TOK * HDIM;

    static h16 *p_x = nullptr;
    static cudaStream_t sR = nullptr, sS = nullptr;
    static cudaEvent_t ev0 = nullptr, evR = nullptr, evS = nullptr;
    static bool init = false;
    if (!init) {
        cudaGetSymbolAddress((void**)&p_x, g_x);
        cudaFuncSetAttribute(gemm13_kernel, cudaFuncAttributeMaxDynamicSharedMemorySize, SMEMB);
        cudaFuncSetAttribute(gemm2_kernel,  cudaFuncAttributeMaxDynamicSharedMemorySize, SMEMB);
        cudaStreamCreateWithFlags(&sR, cudaStreamNonBlocking);
        cudaStreamCreateWithFlags(&sS, cudaStreamNonBlocking);
        cudaEventCreateWithFlags(&ev0, cudaEventDisableTiming);
        cudaEventCreateWithFlags(&evR, cudaEventDisableTiming);
        cudaEventCreateWithFlags(&evS, cudaEventDisableTiming);
        init = true;
    }

    const size_t xn4 = (size_t)T_TOK * HDIM / 4;

    // fork side streams
    cudaEventRecord(ev0, 0);
    cudaStreamWaitEvent(sR, ev0, 0);
    cudaStreamWaitEvent(sS, ev0, 0);

    // side R: routing
    reset_kernel<<<1, 32, 0, sR>>>();
    router_kernel<<<T_TOK / 4, 256, 0, sR>>>(x, rw, rb, logits);
    cudaEventRecord(evR, sR);

    // side S: zero the output (gemm2 is all-atomic)
    zero_out<<<2048, 256, 0, sS>>>((float4*)out, (size_t)T_TOK * HDIM / 4);
    cudaEventRecord(evS, sS);

    // main: x -> fp16 (only remaining pre-conversion)
    split1_arr<<<4096, 256>>>(x, p_x, xn4);

    // gemm13, all 9 passes (weights consumed as fp32 in-kernel)
    cudaStreamWaitEvent(0, evR, 0);
    dim3 g13(FDIM / 128, T_TOK / 128, 9);
    gemm13_kernel<<<g13, 512, SMEMB>>>(w1, w3, sw1, sw3);

    // gemm2, all 9 passes, atomic accumulate
    cudaStreamWaitEvent(0, evS, 0);
    dim3 g2(HDIM / 256, T_TOK / 128, 9);
    gemm2_kernel<<<g2, 512, SMEMB>>>(out, w2, sw2);
}

// round 15
// speedup vs baseline: 1.5332x; 1.5332x over previous
#include <cuda_runtime.h>
#include <cuda_fp16.h>
#include <cstdint>

using h16 = __half;

#define T_TOK 8192
#define HDIM  2048
#define FDIM  4096
#define NEXP  8
#define BK    64

static const size_t WSZ = (size_t)FDIM * HDIM;

// ---------------- persistent scratch ----------------
__device__ int   g_cnt[NEXP];
__device__ int   g_list[NEXP][T_TOK];
__device__ float g_wt[NEXP][T_TOK];

__device__ h16 g_x[(size_t)T_TOK * HDIM];
__device__ h16 g_w1[9 * (size_t)FDIM * HDIM];
__device__ h16 g_w3[9 * (size_t)FDIM * HDIM];
__device__ h16 g_w2[9 * (size_t)FDIM * HDIM];
__device__ h16 g_act[9 * (size_t)T_TOK * FDIM];

// ---------------- helpers ----------------
__device__ __forceinline__ uint32_t sm_addr(const void* p) {
    return (uint32_t)__cvta_generic_to_shared(p);
}
__device__ __forceinline__ void ldsm_x4(uint32_t* r, const h16* p) {
    uint32_t a = sm_addr(p);
    asm volatile("ldmatrix.sync.aligned.m8n8.x4.shared.b16 {%0,%1,%2,%3}, [%4];\n"
                 : "=r"(r[0]), "=r"(r[1]), "=r"(r[2]), "=r"(r[3]) : "r"(a));
}
__device__ __forceinline__ void mma_f16(float* d, const uint32_t* a, const uint32_t* b) {
    asm volatile(
        "mma.sync.aligned.m16n8k16.row.col.f32.f16.f16.f32 "
        "{%0,%1,%2,%3}, {%4,%5,%6,%7}, {%8,%9}, {%0,%1,%2,%3};\n"
        : "+f"(d[0]), "+f"(d[1]), "+f"(d[2]), "+f"(d[3])
        : "r"(a[0]), "r"(a[1]), "r"(a[2]), "r"(a[3]), "r"(b[0]), "r"(b[1]));
}
__device__ __forceinline__ uint32_t pack2h(h16 a, h16 b) {
    union { __half2 v; uint32_t u; } t;
    t.v = __halves2half2(a, b);
    return t.u;
}
__device__ __forceinline__ void cp16(h16* dst, const h16* src, bool valid) {
    uint32_t d = sm_addr(dst);
    int sz = valid ? 16 : 0;
    asm volatile("cp.async.cg.shared.global [%0], [%1], 16, %2;\n"
                 :: "r"(d), "l"(src), "r"(sz));
}
#define CP_COMMIT() asm volatile("cp.async.commit_group;\n" ::: "memory")
#define CP_WAIT(n)  asm volatile("cp.async.wait_group %0;\n" :: "n"(n) : "memory")

__device__ __forceinline__ void red_add2(float* p, float a, float b) {
    asm volatile("red.global.add.v2.f32 [%0], {%1, %2};"
                 :: "l"(p), "f"(a), "f"(b) : "memory");
}

// ---------------- conversions ----------------
__device__ __forceinline__ void conv_loop(const float* __restrict__ src,
                                          h16* __restrict__ dst, size_t n4)
{
    size_t i = blockIdx.x * (size_t)blockDim.x + threadIdx.x;
    size_t stride = (size_t)gridDim.x * blockDim.x;
    const float4* s4 = (const float4*)src;
    for (; i < n4; i += stride) {
        float4 v = s4[i];
        *reinterpret_cast<uint2*>(dst + i * 4) = make_uint2(
            pack2h(__float2half_rn(v.x), __float2half_rn(v.y)),
            pack2h(__float2half_rn(v.z), __float2half_rn(v.w)));
    }
}

__global__ void __launch_bounds__(256) split5(
    const float* s0, h16* d0, size_t n0,
    const float* s1, h16* d1, size_t n1,
    const float* s2, h16* d2, size_t n2,
    const float* s3, h16* d3, size_t n3,
    const float* s4, h16* d4, size_t n4)
{
    switch (blockIdx.z) {
        case 0: conv_loop(s0, d0, n0); break;
        case 1: conv_loop(s1, d1, n1); break;
        case 2: conv_loop(s2, d2, n2); break;
        case 3: conv_loop(s3, d3, n3); break;
        default: conv_loop(s4, d4, n4); break;
    }
}
__global__ void __launch_bounds__(256) split2(
    const float* s0, h16* d0, size_t n0,
    const float* s1, h16* d1, size_t n1)
{
    if (blockIdx.z == 0) conv_loop(s0, d0, n0);
    else                 conv_loop(s1, d1, n1);
}

__global__ void reset_kernel() {
    if (threadIdx.x < NEXP) g_cnt[threadIdx.x] = 0;
}

__global__ void __launch_bounds__(256) zero_out(float4* __restrict__ out, size_t n4)
{
    size_t i = blockIdx.x * (size_t)blockDim.x + threadIdx.x;
    size_t stride = (size_t)gridDim.x * blockDim.x;
    const float4 z = make_float4(0.f, 0.f, 0.f, 0.f);
    for (; i < n4; i += stride) out[i] = z;
}

// ---------------- router: 4 tokens per block ----------------
__global__ void __launch_bounds__(256) router_kernel(
    const float* __restrict__ X, const float* __restrict__ RW,
    const float* __restrict__ RB, float* __restrict__ LOG)
{
    __shared__ float slog[4][NEXP];
    const int tid  = threadIdx.x;
    const int sub  = tid >> 6;
    const int stid = tid & 63;
    const int t    = blockIdx.x * 4 + sub;

    const int w    = stid >> 5;
    const int lane = stid & 31;

    const float* xrow = X + (size_t)t * HDIM;
    #pragma unroll
    for (int eo = 0; eo < 4; eo++) {
        int e = w + eo * 2;
        const float* rw = RW + (size_t)e * HDIM;
        float s = 0.f;
        for (int i = lane; i < HDIM; i += 32) s += xrow[i] * rw[i];
        #pragma unroll
        for (int off = 16; off > 0; off >>= 1) s += __shfl_xor_sync(0xffffffffu, s, off);
        if (lane == 0) slog[sub][e] = s + RB[e];
    }
    __syncthreads();

    if (stid == 0) {
        float l[NEXP];
        float m = -1e30f;
        #pragma unroll
        for (int e = 0; e < NEXP; e++) {
            l[e] = slog[sub][e];
            LOG[(size_t)t * NEXP + e] = l[e];
            m = fmaxf(m, l[e]);
        }
        float p[NEXP];
        #pragma unroll
        for (int e = 0; e < NEXP; e++) p[e] = __expf(l[e] - m);
        int i0 = 0;
        #pragma unroll
        for (int e = 1; e < NEXP; e++) if (l[e] > l[i0]) i0 = e;
        int i1 = -1;
        #pragma unroll
        for (int e = 0; e < NEXP; e++) {
            if (e == i0) continue;
            if (i1 < 0 || l[e] > l[i1]) i1 = e;
        }
        float ws = p[i0] + p[i1];
        float w0 = p[i0] / ws, w1 = p[i1] / ws;
        int p0 = atomicAdd(&g_cnt[i0], 1);
        g_list[i0][p0] = t; g_wt[i0][p0] = w0;
        int p1 = atomicAdd(&g_cnt[i1], 1);
        g_list[i1][p1] = t; g_wt[i1][p1] = w1;
    }
}

// shared tile geometry: A 128x64 (stride 72), B 256x64 (stride 72)
#define A_ST   72
#define A_SZ   (128 * 72)
#define B_SZ   (256 * 72)
#define SSTG   (A_SZ + B_SZ)
#define SMEMB  (3 * SSTG * 2)

// ---------------- GEMM13 (all passes): act[z] = silu(X w1^T) * (X w3^T) ----------------
__global__ void __maxnreg__(120) gemm13_kernel()
{
    const int z = blockIdx.z;
    const int count = (z == NEXP) ? T_TOK : g_cnt[z];
    const int m0 = blockIdx.y * 128;
    if (m0 >= count) return;
    const int n0 = blockIdx.x * 128;

    extern __shared__ __align__(16) h16 sm[];

    const h16* __restrict__ W1 = g_w1 + (size_t)z * WSZ;
    const h16* __restrict__ W3 = g_w3 + (size_t)z * WSZ;

    const int tid  = threadIdx.x;
    const int lane = tid & 31;
    const int warp = tid >> 5;
    const int wm = (warp & 3) * 32;
    const int wn = (warp >> 2) * 32;

    const int r0  = tid >> 3;
    const int c16 = tid & 7;
    const int aoff = r0 * A_ST + c16 * 8;

    bool av0 = (m0 + r0) < count;
    bool av1 = (m0 + r0 + 64) < count;
    int tok0 = 0, tok1 = 0;
    if (av0) tok0 = (z == NEXP) ? (m0 + r0)      : g_list[z][m0 + r0];
    if (av1) tok1 = (z == NEXP) ? (m0 + r0 + 64) : g_list[z][m0 + r0 + 64];
    const h16* asrc0 = g_x + (size_t)tok0 * HDIM + c16 * 8;
    const h16* asrc1 = g_x + (size_t)tok1 * HDIM + c16 * 8;
    const h16* bsrc0 = W1 + (size_t)(n0 + r0)      * HDIM + c16 * 8;
    const h16* bsrc1 = W1 + (size_t)(n0 + r0 + 64) * HDIM + c16 * 8;
    const h16* bsrc2 = W3 + (size_t)(n0 + r0)      * HDIM + c16 * 8;
    const h16* bsrc3 = W3 + (size_t)(n0 + r0 + 64) * HDIM + c16 * 8;

    float acc1[2][4][4];
    float acc3[2][4][4];
    #pragma unroll
    for (int i = 0; i < 2; i++)
        #pragma unroll
        for (int j = 0; j < 4; j++)
            #pragma unroll
            for (int q = 0; q < 4; q++) { acc1[i][j][q] = 0.f; acc3[i][j][q] = 0.f; }

    const int a_r = (lane & 7) + ((lane >> 3) & 1) * 8;
    const int a_c = ((lane >> 4) & 1) * 8;
    const int b_r = (lane & 7) + ((lane >> 4) & 1) * 8;
    const int b_c = ((lane >> 3) & 1) * 8;

    const int KT = HDIM / BK;   // 32

    auto load_stage = [&](int s, int k0) {
        h16* base = sm + s * SSTG;
        cp16(base + aoff,              asrc0 + k0, av0);
        cp16(base + aoff + 64 * A_ST,  asrc1 + k0, av1);
        h16* bb = base + A_SZ;
        cp16(bb + aoff,                bsrc0 + k0, true);
        cp16(bb + aoff +  64 * A_ST,   bsrc1 + k0, true);
        cp16(bb + aoff + 128 * A_ST,   bsrc2 + k0, true);
        cp16(bb + aoff + 192 * A_ST,   bsrc3 + k0, true);
        CP_COMMIT();
    };

    load_stage(0, 0);
    load_stage(1, BK);

    for (int kt = 0; kt < KT; kt++) {
        if (kt + 1 < KT) { CP_WAIT(1); } else { CP_WAIT(0); }
        __syncthreads();
        if (kt + 2 < KT) load_stage((kt + 2) % 3, (kt + 2) * BK);

        const h16* base = sm + (kt % 3) * SSTG;
        const h16* bB = base + A_SZ;

        #pragma unroll
        for (int kk = 0; kk < BK; kk += 16) {
            uint32_t a[2][4];
            ldsm_x4(a[0], base + (wm +      a_r) * A_ST + kk + a_c);
            ldsm_x4(a[1], base + (wm + 16 + a_r) * A_ST + kk + a_c);
            #pragma unroll
            for (int pb = 0; pb < 2; pb++) {
                uint32_t b1[4], b3[4];
                ldsm_x4(b1, bB + (wn + pb * 16 + b_r) * A_ST + kk + b_c);
                ldsm_x4(b3, bB + (128 + wn + pb * 16 + b_r) * A_ST + kk + b_c);
                #pragma unroll
                for (int mi = 0; mi < 2; mi++) {
                    mma_f16(acc1[mi][pb * 2 + 0], a[mi], &b1[0]);
                    mma_f16(acc1[mi][pb * 2 + 1], a[mi], &b1[2]);
                    mma_f16(acc3[mi][pb * 2 + 0], a[mi], &b3[0]);
                    mma_f16(acc3[mi][pb * 2 + 1], a[mi], &b3[2]);
                }
            }
        }
    }

    h16* actz = g_act + (size_t)z * T_TOK * FDIM;
    #pragma unroll
    for (int mi = 0; mi < 2; mi++) {
        #pragma unroll
        for (int q2 = 0; q2 < 2; q2++) {
            int r_loc = m0 + wm + mi * 16 + (lane >> 2) + q2 * 8;
            if (r_loc >= count) continue;
            h16* arow = actz + (size_t)r_loc * FDIM;
            #pragma unroll
            for (int ni = 0; ni < 4; ni++) {
                int c = n0 + wn + ni * 8 + (lane & 3) * 2;
                float a0 = acc1[mi][ni][q2 * 2 + 0];
                float a1 = acc1[mi][ni][q2 * 2 + 1];
                float b0 = acc3[mi][ni][q2 * 2 + 0];
                float b1 = acc3[mi][ni][q2 * 2 + 1];
                float v0 = (a0 / (1.f + __expf(-a0))) * b0;
                float v1 = (a1 / (1.f + __expf(-a1))) * b1;
                *reinterpret_cast<uint32_t*>(arow + c) =
                    pack2h(__float2half_rn(v0), __float2half_rn(v1));
            }
        }
    }
}

// ---------------- GEMM2 (all passes, atomic): out += w * (act[z] @ w2^T) ----------------
__global__ void __maxnreg__(120) gemm2_kernel(float* __restrict__ OUT)
{
    const int z = blockIdx.z;
    const int count = (z == NEXP) ? T_TOK : g_cnt[z];
    const int m0 = blockIdx.y * 128;
    if (m0 >= count) return;
    const int n0 = blockIdx.x * 256;

    extern __shared__ __align__(16) h16 sm[];

    const h16* __restrict__ W2 = g_w2 + (size_t)z * WSZ;
    const h16* __restrict__ actz = g_act + (size_t)z * T_TOK * FDIM;

    const int tid  = threadIdx.x;
    const int lane = tid & 31;
    const int warp = tid >> 5;
    const int wm = (warp & 3) * 32;
    const int wn = (warp >> 2) * 64;

    const int r0  = tid >> 3;
    const int c16 = tid & 7;
    const int aoff = r0 * A_ST + c16 * 8;

    const bool av0 = (m0 + r0) < count;
    const bool av1 = (m0 + r0 + 64) < count;
    const h16* asrc0 = actz + (size_t)(av0 ? (m0 + r0)      : 0) * FDIM + c16 * 8;
    const h16* asrc1 = actz + (size_t)(av1 ? (m0 + r0 + 64) : 0) * FDIM + c16 * 8;
    const h16* bsrc0 = W2 + (size_t)(n0 + r0)       * FDIM + c16 * 8;
    const h16* bsrc1 = W2 + (size_t)(n0 + r0 +  64) * FDIM + c16 * 8;
    const h16* bsrc2 = W2 + (size_t)(n0 + r0 + 128) * FDIM + c16 * 8;
    const h16* bsrc3 = W2 + (size_t)(n0 + r0 + 192) * FDIM + c16 * 8;

    float acc[2][8][4];
    #pragma unroll
    for (int i = 0; i < 2; i++)
        #pragma unroll
        for (int j = 0; j < 8; j++)
            #pragma unroll
            for (int q = 0; q < 4; q++) acc[i][j][q] = 0.f;

    const int a_r = (lane & 7) + ((lane >> 3) & 1) * 8;
    const int a_c = ((lane >> 4) & 1) * 8;
    const int b_r = (lane & 7) + ((lane >> 4) & 1) * 8;
    const int b_c = ((lane >> 3) & 1) * 8;

    const int KT = FDIM / BK;   // 64

    auto load_stage = [&](int s, int k0) {
        h16* base = sm + s * SSTG;
        cp16(base + aoff,             asrc0 + k0, av0);
        cp16(base + aoff + 64 * A_ST, asrc1 + k0, av1);
        h16* bb = base + A_SZ;
        cp16(bb + aoff,               bsrc0 + k0, true);
        cp16(bb + aoff +  64 * A_ST,  bsrc1 + k0, true);
        cp16(bb + aoff + 128 * A_ST,  bsrc2 + k0, true);
        cp16(bb + aoff + 192 * A_ST,  bsrc3 + k0, true);
        CP_COMMIT();
    };

    load_stage(0, 0);
    load_stage(1, BK);

    for (int kt = 0; kt < KT; kt++) {
        if (kt + 1 < KT) { CP_WAIT(1); } else { CP_WAIT(0); }
        __syncthreads();
        if (kt + 2 < KT) load_stage((kt + 2) % 3, (kt + 2) * BK);

        const h16* base = sm + (kt % 3) * SSTG;
        const h16* bB = base + A_SZ;

        #pragma unroll
        for (int kk = 0; kk < BK; kk += 16) {
            uint32_t a[2][4];
            ldsm_x4(a[0], base + (wm +      a_r) * A_ST + kk + a_c);
            ldsm_x4(a[1], base + (wm + 16 + a_r) * A_ST + kk + a_c);
            #pragma unroll
            for (int pb = 0; pb < 4; pb++) {
                uint32_t b[4];
                ldsm_x4(b, bB + (wn + pb * 16 + b_r) * A_ST + kk + b_c);
                #pragma unroll
                for (int mi = 0; mi < 2; mi++) {
                    mma_f16(acc[mi][pb * 2 + 0], a[mi], &b[0]);
                    mma_f16(acc[mi][pb * 2 + 1], a[mi], &b[2]);
                }
            }
        }
    }

    #pragma unroll
    for (int mi = 0; mi < 2; mi++) {
        #pragma unroll
        for (int q2 = 0; q2 < 2; q2++) {
            int r_loc = m0 + wm + mi * 16 + (lane >> 2) + q2 * 8;
            if (r_loc >= count) continue;
            int tok; float wgt;
            if (z == NEXP) { tok = r_loc; wgt = 1.f; }
            else { tok = g_list[z][r_loc]; wgt = g_wt[z][r_loc]; }
            float* orow = OUT + (size_t)tok * HDIM;
            #pragma unroll
            for (int ni = 0; ni < 8; ni++) {
                int c = n0 + wn + ni * 8 + (lane & 3) * 2;
                red_add2(&orow[c],
                         wgt * acc[mi][ni][q2 * 2 + 0],
                         wgt * acc[mi][ni][q2 * 2 + 1]);
            }
        }
    }
}

// ---------------- launch ----------------
extern "C" void kernel_launch(void* const* d_in, const int* in_sizes, int n_in,
                              void* d_out, int out_size)
{
    const float* x   = (const float*)d_in[0];
    const float* rw  = (const float*)d_in[1];
    const float* rb  = (const float*)d_in[2];
    const float* w1  = (const float*)d_in[3];
    const float* w2  = (const float*)d_in[4];
    const float* w3  = (const float*)d_in[5];
    const float* sw1 = (const float*)d_in[6];
    const float* sw2 = (const float*)d_in[7];
    const float* sw3 = (const float*)d_in[8];

    float* out    = (float*)d_out;
    float* logits = out + (size_t)T_TOK * HDIM;

    static h16 *p_x = nullptr, *p_w1, *p_w3, *p_w2;
    static cudaStream_t sR = nullptr, sS = nullptr;
    static cudaEvent_t ev0 = nullptr, evR = nullptr, evS = nullptr;
    static bool init = false;
    if (!init) {
        cudaGetSymbolAddress((void**)&p_x,  g_x);
        cudaGetSymbolAddress((void**)&p_w1, g_w1);
        cudaGetSymbolAddress((void**)&p_w3, g_w3);
        cudaGetSymbolAddress((void**)&p_w2, g_w2);
        cudaFuncSetAttribute(gemm13_kernel, cudaFuncAttributeMaxDynamicSharedMemorySize, SMEMB);
        cudaFuncSetAttribute(gemm2_kernel,  cudaFuncAttributeMaxDynamicSharedMemorySize, SMEMB);
        cudaStreamCreateWithFlags(&sR, cudaStreamNonBlocking);
        cudaStreamCreateWithFlags(&sS, cudaStreamNonBlocking);
        cudaEventCreateWithFlags(&ev0, cudaEventDisableTiming);
        cudaEventCreateWithFlags(&evR, cudaEventDisableTiming);
        cudaEventCreateWithFlags(&evS, cudaEventDisableTiming);
        init = true;
    }

    const size_t xn4 = (size_t)T_TOK * HDIM / 4;
    const size_t wn4 = (size_t)NEXP * WSZ / 4;
    const size_t sn4 = WSZ / 4;

    // fork side streams from the (captured) default stream
    cudaEventRecord(ev0, 0);
    cudaStreamWaitEvent(sR, ev0, 0);
    cudaStreamWaitEvent(sS, ev0, 0);

    reset_kernel<<<1, 32, 0, sR>>>();
    router_kernel<<<T_TOK / 4, 256, 0, sR>>>(x, rw, rb, logits);
    cudaEventRecord(evR, sR);

    {
        dim3 g(4096, 1, 2);
        split2<<<g, 256, 0, sS>>>(w2, p_w2, wn4,
                                  sw2, p_w2 + NEXP * WSZ, sn4);
    }
    zero_out<<<2048, 256, 0, sS>>>((float4*)out,
                                   (size_t)T_TOK * HDIM / 4);
    cudaEventRecord(evS, sS);

    {
        dim3 g(3072, 1, 5);
        split5<<<g, 256>>>(x,  p_x,  xn4,
                           w1, p_w1, wn4,
                           w3, p_w3, wn4,
                           sw1, p_w1 + NEXP * WSZ, sn4,
                           sw3, p_w3 + NEXP * WSZ, sn4);
    }

    cudaStreamWaitEvent(0, evR, 0);   // router/reset done before gemm13
    dim3 g13(FDIM / 128, T_TOK / 128, 9);
    gemm13_kernel<<<g13, 512, SMEMB>>>();

    cudaStreamWaitEvent(0, evS, 0);   // w2 split + zero done before gemm2
    dim3 g2(HDIM / 256, T_TOK / 128, 9);
    gemm2_kernel<<<g2, 512, SMEMB>>>(out);
}

// round 16
// speedup vs baseline: 1.5748x; 1.0272x over previous
#include <cuda_runtime.h>
#include <cuda_fp16.h>
#include <cstdint>

using h16 = __half;

#define T_TOK 8192
#define HDIM  2048
#define FDIM  4096
#define NEXP  8
#define BK    64

static const size_t WSZ = (size_t)FDIM * HDIM;

// ---------------- persistent scratch ----------------
__device__ int   g_cnt[NEXP];
__device__ int   g_list[NEXP][T_TOK];
__device__ float g_wt[NEXP][T_TOK];

__device__ h16 g_x[(size_t)T_TOK * HDIM];
__device__ h16 g_w1[9 * (size_t)FDIM * HDIM];
__device__ h16 g_w3[9 * (size_t)FDIM * HDIM];
__device__ h16 g_w2[9 * (size_t)FDIM * HDIM];
__device__ h16 g_act[9 * (size_t)T_TOK * FDIM];

// ---------------- helpers ----------------
__device__ __forceinline__ uint32_t sm_addr(const void* p) {
    return (uint32_t)__cvta_generic_to_shared(p);
}
__device__ __forceinline__ void ldsm_x4(uint32_t* r, const h16* p) {
    uint32_t a = sm_addr(p);
    asm volatile("ldmatrix.sync.aligned.m8n8.x4.shared.b16 {%0,%1,%2,%3}, [%4];\n"
                 : "=r"(r[0]), "=r"(r[1]), "=r"(r[2]), "=r"(r[3]) : "r"(a));
}
__device__ __forceinline__ void mma_f16(float* d, const uint32_t* a, const uint32_t* b) {
    asm volatile(
        "mma.sync.aligned.m16n8k16.row.col.f32.f16.f16.f32 "
        "{%0,%1,%2,%3}, {%4,%5,%6,%7}, {%8,%9}, {%0,%1,%2,%3};\n"
        : "+f"(d[0]), "+f"(d[1]), "+f"(d[2]), "+f"(d[3])
        : "r"(a[0]), "r"(a[1]), "r"(a[2]), "r"(a[3]), "r"(b[0]), "r"(b[1]));
}
__device__ __forceinline__ uint32_t pack2h(h16 a, h16 b) {
    union { __half2 v; uint32_t u; } t;
    t.v = __halves2half2(a, b);
    return t.u;
}
__device__ __forceinline__ void cp16(h16* dst, const h16* src, bool valid) {
    uint32_t d = sm_addr(dst);
    int sz = valid ? 16 : 0;
    asm volatile("cp.async.cg.shared.global [%0], [%1], 16, %2;\n"
                 :: "r"(d), "l"(src), "r"(sz));
}
#define CP_COMMIT() asm volatile("cp.async.commit_group;\n" ::: "memory")
#define CP_WAIT(n)  asm volatile("cp.async.wait_group %0;\n" :: "n"(n) : "memory")

__device__ __forceinline__ void red_add2(float* p, float a, float b) {
    asm volatile("red.global.add.v2.f32 [%0], {%1, %2};"
                 :: "l"(p), "f"(a), "f"(b) : "memory");
}

// ---------------- conversions ----------------
__device__ __forceinline__ void conv_loop(const float* __restrict__ src,
                                          h16* __restrict__ dst, size_t n4)
{
    size_t i = blockIdx.x * (size_t)blockDim.x + threadIdx.x;
    size_t stride = (size_t)gridDim.x * blockDim.x;
    const float4* s4 = (const float4*)src;
    for (; i < n4; i += stride) {
        float4 v = s4[i];
        *reinterpret_cast<uint2*>(dst + i * 4) = make_uint2(
            pack2h(__float2half_rn(v.x), __float2half_rn(v.y)),
            pack2h(__float2half_rn(v.z), __float2half_rn(v.w)));
    }
}

__global__ void __launch_bounds__(256) split5(
    const float* s0, h16* d0, size_t n0,
    const float* s1, h16* d1, size_t n1,
    const float* s2, h16* d2, size_t n2,
    const float* s3, h16* d3, size_t n3,
    const float* s4, h16* d4, size_t n4)
{
    switch (blockIdx.z) {
        case 0: conv_loop(s0, d0, n0); break;
        case 1: conv_loop(s1, d1, n1); break;
        case 2: conv_loop(s2, d2, n2); break;
        case 3: conv_loop(s3, d3, n3); break;
        default: conv_loop(s4, d4, n4); break;
    }
}
__global__ void __launch_bounds__(256) split2(
    const float* s0, h16* d0, size_t n0,
    const float* s1, h16* d1, size_t n1)
{
    if (blockIdx.z == 0) conv_loop(s0, d0, n0);
    else                 conv_loop(s1, d1, n1);
}

__global__ void reset_kernel() {
    if (threadIdx.x < NEXP) g_cnt[threadIdx.x] = 0;
}

__global__ void __launch_bounds__(256) zero_out(float4* __restrict__ out, size_t n4)
{
    size_t i = blockIdx.x * (size_t)blockDim.x + threadIdx.x;
    size_t stride = (size_t)gridDim.x * blockDim.x;
    const float4 z = make_float4(0.f, 0.f, 0.f, 0.f);
    for (; i < n4; i += stride) out[i] = z;
}

// ---------------- router: 4 tokens per block ----------------
__global__ void __launch_bounds__(256) router_kernel(
    const float* __restrict__ X, const float* __restrict__ RW,
    const float* __restrict__ RB, float* __restrict__ LOG)
{
    __shared__ float slog[4][NEXP];
    const int tid  = threadIdx.x;
    const int sub  = tid >> 6;
    const int stid = tid & 63;
    const int t    = blockIdx.x * 4 + sub;

    const int w    = stid >> 5;
    const int lane = stid & 31;

    const float* xrow = X + (size_t)t * HDIM;
    #pragma unroll
    for (int eo = 0; eo < 4; eo++) {
        int e = w + eo * 2;
        const float* rw = RW + (size_t)e * HDIM;
        float s = 0.f;
        for (int i = lane; i < HDIM; i += 32) s += xrow[i] * rw[i];
        #pragma unroll
        for (int off = 16; off > 0; off >>= 1) s += __shfl_xor_sync(0xffffffffu, s, off);
        if (lane == 0) slog[sub][e] = s + RB[e];
    }
    __syncthreads();

    if (stid == 0) {
        float l[NEXP];
        float m = -1e30f;
        #pragma unroll
        for (int e = 0; e < NEXP; e++) {
            l[e] = slog[sub][e];
            LOG[(size_t)t * NEXP + e] = l[e];
            m = fmaxf(m, l[e]);
        }
        float p[NEXP];
        #pragma unroll
        for (int e = 0; e < NEXP; e++) p[e] = __expf(l[e] - m);
        int i0 = 0;
        #pragma unroll
        for (int e = 1; e < NEXP; e++) if (l[e] > l[i0]) i0 = e;
        int i1 = -1;
        #pragma unroll
        for (int e = 0; e < NEXP; e++) {
            if (e == i0) continue;
            if (i1 < 0 || l[e] > l[i1]) i1 = e;
        }
        float ws = p[i0] + p[i1];
        float w0 = p[i0] / ws, w1 = p[i1] / ws;
        int p0 = atomicAdd(&g_cnt[i0], 1);
        g_list[i0][p0] = t; g_wt[i0][p0] = w0;
        int p1 = atomicAdd(&g_cnt[i1], 1);
        g_list[i1][p1] = t; g_wt[i1][p1] = w1;
    }
}

// shared tile geometry: A 128x64 (stride 72), B 256x64 (stride 72)
#define A_ST   72
#define A_SZ   (128 * 72)
#define B_SZ   (256 * 72)
#define SSTG   (A_SZ + B_SZ)
#define SMEMB  (3 * SSTG * 2)

// ---------------- GEMM13 (all passes): act[z] = silu(X w1^T) * (X w3^T) ----------------
__global__ void __launch_bounds__(512) gemm13_kernel()
{
    const int z = blockIdx.z;
    const int count = (z == NEXP) ? T_TOK : g_cnt[z];
    const int m0 = blockIdx.y * 128;
    if (m0 >= count) return;
    const int n0 = blockIdx.x * 128;

    extern __shared__ __align__(16) h16 sm[];

    const h16* __restrict__ W1 = g_w1 + (size_t)z * WSZ;
    const h16* __restrict__ W3 = g_w3 + (size_t)z * WSZ;

    const int tid  = threadIdx.x;
    const int lane = tid & 31;
    const int warp = tid >> 5;
    const int wm = (warp & 3) * 32;
    const int wn = (warp >> 2) * 32;

    const int r0  = tid >> 3;
    const int c16 = tid & 7;
    const int aoff = r0 * A_ST + c16 * 8;

    bool av0 = (m0 + r0) < count;
    bool av1 = (m0 + r0 + 64) < count;
    int tok0 = 0, tok1 = 0;
    if (av0) tok0 = (z == NEXP) ? (m0 + r0)      : g_list[z][m0 + r0];
    if (av1) tok1 = (z == NEXP) ? (m0 + r0 + 64) : g_list[z][m0 + r0 + 64];
    const h16* asrc0 = g_x + (size_t)tok0 * HDIM + c16 * 8;
    const h16* asrc1 = g_x + (size_t)tok1 * HDIM + c16 * 8;
    const h16* bsrc0 = W1 + (size_t)(n0 + r0)      * HDIM + c16 * 8;
    const h16* bsrc1 = W1 + (size_t)(n0 + r0 + 64) * HDIM + c16 * 8;
    const h16* bsrc2 = W3 + (size_t)(n0 + r0)      * HDIM + c16 * 8;
    const h16* bsrc3 = W3 + (size_t)(n0 + r0 + 64) * HDIM + c16 * 8;

    float acc1[2][4][4];
    float acc3[2][4][4];
    #pragma unroll
    for (int i = 0; i < 2; i++)
        #pragma unroll
        for (int j = 0; j < 4; j++)
            #pragma unroll
            for (int q = 0; q < 4; q++) { acc1[i][j][q] = 0.f; acc3[i][j][q] = 0.f; }

    const int a_r = (lane & 7) + ((lane >> 3) & 1) * 8;
    const int a_c = ((lane >> 4) & 1) * 8;
    const int b_r = (lane & 7) + ((lane >> 4) & 1) * 8;
    const int b_c = ((lane >> 3) & 1) * 8;

    const int KT = HDIM / BK;   // 32

    auto load_stage = [&](int s, int k0) {
        h16* base = sm + s * SSTG;
        cp16(base + aoff,              asrc0 + k0, av0);
        cp16(base + aoff + 64 * A_ST,  asrc1 + k0, av1);
        h16* bb = base + A_SZ;
        cp16(bb + aoff,                bsrc0 + k0, true);
        cp16(bb + aoff +  64 * A_ST,   bsrc1 + k0, true);
        cp16(bb + aoff + 128 * A_ST,   bsrc2 + k0, true);
        cp16(bb + aoff + 192 * A_ST,   bsrc3 + k0, true);
        CP_COMMIT();
    };

    load_stage(0, 0);
    load_stage(1, BK);

    for (int kt = 0; kt < KT; kt++) {
        if (kt + 1 < KT) { CP_WAIT(1); } else { CP_WAIT(0); }
        __syncthreads();
        if (kt + 2 < KT) load_stage((kt + 2) % 3, (kt + 2) * BK);

        const h16* base = sm + (kt % 3) * SSTG;
        const h16* bB = base + A_SZ;

        #pragma unroll
        for (int kk = 0; kk < BK; kk += 16) {
            uint32_t a[2][4];
            ldsm_x4(a[0], base + (wm +      a_r) * A_ST + kk + a_c);
            ldsm_x4(a[1], base + (wm + 16 + a_r) * A_ST + kk + a_c);
            #pragma unroll
            for (int pb = 0; pb < 2; pb++) {
                uint32_t b1[4], b3[4];
                ldsm_x4(b1, bB + (wn + pb * 16 + b_r) * A_ST + kk + b_c);
                ldsm_x4(b3, bB + (128 + wn + pb * 16 + b_r) * A_ST + kk + b_c);
                #pragma unroll
                for (int mi = 0; mi < 2; mi++) {
                    mma_f16(acc1[mi][pb * 2 + 0], a[mi], &b1[0]);
                    mma_f16(acc1[mi][pb * 2 + 1], a[mi], &b1[2]);
                    mma_f16(acc3[mi][pb * 2 + 0], a[mi], &b3[0]);
                    mma_f16(acc3[mi][pb * 2 + 1], a[mi], &b3[2]);
                }
            }
        }
    }

    h16* actz = g_act + (size_t)z * T_TOK * FDIM;
    #pragma unroll
    for (int mi = 0; mi < 2; mi++) {
        #pragma unroll
        for (int q2 = 0; q2 < 2; q2++) {
            int r_loc = m0 + wm + mi * 16 + (lane >> 2) + q2 * 8;
            if (r_loc >= count) continue;
            h16* arow = actz + (size_t)r_loc * FDIM;
            #pragma unroll
            for (int ni = 0; ni < 4; ni++) {
                int c = n0 + wn + ni * 8 + (lane & 3) * 2;
                float a0 = acc1[mi][ni][q2 * 2 + 0];
                float a1 = acc1[mi][ni][q2 * 2 + 1];
                float b0 = acc3[mi][ni][q2 * 2 + 0];
                float b1 = acc3[mi][ni][q2 * 2 + 1];
                float v0 = (a0 / (1.f + __expf(-a0))) * b0;
                float v1 = (a1 / (1.f + __expf(-a1))) * b1;
                *reinterpret_cast<uint32_t*>(arow + c) =
                    pack2h(__float2half_rn(v0), __float2half_rn(v1));
            }
        }
    }
}

// ---------------- GEMM2 (all passes, atomic): out += w * (act[z] @ w2^T) ----------------
__global__ void __launch_bounds__(512) gemm2_kernel(float* __restrict__ OUT)
{
    const int z = blockIdx.z;
    const int count = (z == NEXP) ? T_TOK : g_cnt[z];
    const int m0 = blockIdx.y * 128;
    if (m0 >= count) return;
    const int n0 = blockIdx.x * 256;

    extern __shared__ __align__(16) h16 sm[];

    const h16* __restrict__ W2 = g_w2 + (size_t)z * WSZ;
    const h16* __restrict__ actz = g_act + (size_t)z * T_TOK * FDIM;

    const int tid  = threadIdx.x;
    const int lane = tid & 31;
    const int warp = tid >> 5;
    const int wm = (warp & 3) * 32;
    const int wn = (warp >> 2) * 64;

    const int r0  = tid >> 3;
    const int c16 = tid & 7;
    const int aoff = r0 * A_ST + c16 * 8;

    const bool av0 = (m0 + r0) < count;
    const bool av1 = (m0 + r0 + 64) < count;
    const h16* asrc0 = actz + (size_t)(av0 ? (m0 + r0)      : 0) * FDIM + c16 * 8;
    const h16* asrc1 = actz + (size_t)(av1 ? (m0 + r0 + 64) : 0) * FDIM + c16 * 8;
    const h16* bsrc0 = W2 + (size_t)(n0 + r0)       * FDIM + c16 * 8;
    const h16* bsrc1 = W2 + (size_t)(n0 + r0 +  64) * FDIM + c16 * 8;
    const h16* bsrc2 = W2 + (size_t)(n0 + r0 + 128) * FDIM + c16 * 8;
    const h16* bsrc3 = W2 + (size_t)(n0 + r0 + 192) * FDIM + c16 * 8;

    float acc[2][8][4];
    #pragma unroll
    for (int i = 0; i < 2; i++)
        #pragma unroll
        for (int j = 0; j < 8; j++)
            #pragma unroll
            for (int q = 0; q < 4; q++) acc[i][j][q] = 0.f;

    const int a_r = (lane & 7) + ((lane >> 3) & 1) * 8;
    const int a_c = ((lane >> 4) & 1) * 8;
    const int b_r = (lane & 7) + ((lane >> 4) & 1) * 8;
    const int b_c = ((lane >> 3) & 1) * 8;

    const int KT = FDIM / BK;   // 64

    auto load_stage = [&](int s, int k0) {
        h16* base = sm + s * SSTG;
        cp16(base + aoff,             asrc0 + k0, av0);
        cp16(base + aoff + 64 * A_ST, asrc1 + k0, av1);
        h16* bb = base + A_SZ;
        cp16(bb + aoff,               bsrc0 + k0, true);
        cp16(bb + aoff +  64 * A_ST,  bsrc1 + k0, true);
        cp16(bb + aoff + 128 * A_ST,  bsrc2 + k0, true);
        cp16(bb + aoff + 192 * A_ST,  bsrc3 + k0, true);
        CP_COMMIT();
    };

    load_stage(0, 0);
    load_stage(1, BK);

    for (int kt = 0; kt < KT; kt++) {
        if (kt + 1 < KT) { CP_WAIT(1); } else { CP_WAIT(0); }
        __syncthreads();
        if (kt + 2 < KT) load_stage((kt + 2) % 3, (kt + 2) * BK);

        const h16* base = sm + (kt % 3) * SSTG;
        const h16* bB = base + A_SZ;

        #pragma unroll
        for (int kk = 0; kk < BK; kk += 16) {
            uint32_t a[2][4];
            ldsm_x4(a[0], base + (wm +      a_r) * A_ST + kk + a_c);
            ldsm_x4(a[1], base + (wm + 16 + a_r) * A_ST + kk + a_c);
            #pragma unroll
            for (int pb = 0; pb < 4; pb++) {
                uint32_t b[4];
                ldsm_x4(b, bB + (wn + pb * 16 + b_r) * A_ST + kk + b_c);
                #pragma unroll
                for (int mi = 0; mi < 2; mi++) {
                    mma_f16(acc[mi][pb * 2 + 0], a[mi], &b[0]);
                    mma_f16(acc[mi][pb * 2 + 1], a[mi], &b[2]);
                }
            }
        }
    }

    #pragma unroll
    for (int mi = 0; mi < 2; mi++) {
        #pragma unroll
        for (int q2 = 0; q2 < 2; q2++) {
            int r_loc = m0 + wm + mi * 16 + (lane >> 2) + q2 * 8;
            if (r_loc >= count) continue;
            int tok; float wgt;
            if (z == NEXP) { tok = r_loc; wgt = 1.f; }
            else { tok = g_list[z][r_loc]; wgt = g_wt[z][r_loc]; }
            float* orow = OUT + (size_t)tok * HDIM;
            #pragma unroll
            for (int ni = 0; ni < 8; ni++) {
                int c = n0 + wn + ni * 8 + (lane & 3) * 2;
                red_add2(&orow[c],
                         wgt * acc[mi][ni][q2 * 2 + 0],
                         wgt * acc[mi][ni][q2 * 2 + 1]);
            }
        }
    }
}

// ---------------- launch ----------------
extern "C" void kernel_launch(void* const* d_in, const int* in_sizes, int n_in,
                              void* d_out, int out_size)
{
    const float* x   = (const float*)d_in[0];
    const float* rw  = (const float*)d_in[1];
    const float* rb  = (const float*)d_in[2];
    const float* w1  = (const float*)d_in[3];
    const float* w2  = (const float*)d_in[4];
    const float* w3  = (const float*)d_in[5];
    const float* sw1 = (const float*)d_in[6];
    const float* sw2 = (const float*)d_in[7];
    const float* sw3 = (const float*)d_in[8];

    float* out    = (float*)d_out;
    float* logits = out + (size_t)T_TOK * HDIM;

    static h16 *p_x = nullptr, *p_w1, *p_w3, *p_w2;
    static cudaStream_t sR = nullptr, sS = nullptr;
    static cudaEvent_t ev0 = nullptr, evR = nullptr, evS = nullptr;
    static bool init = false;
    if (!init) {
        cudaGetSymbolAddress((void**)&p_x,  g_x);
        cudaGetSymbolAddress((void**)&p_w1, g_w1);
        cudaGetSymbolAddress((void**)&p_w3, g_w3);
        cudaGetSymbolAddress((void**)&p_w2, g_w2);
        cudaFuncSetAttribute(gemm13_kernel, cudaFuncAttributeMaxDynamicSharedMemorySize, SMEMB);
        cudaFuncSetAttribute(gemm2_kernel,  cudaFuncAttributeMaxDynamicSharedMemorySize, SMEMB);
        cudaStreamCreateWithFlags(&sR, cudaStreamNonBlocking);
        cudaStreamCreateWithFlags(&sS, cudaStreamNonBlocking);
        cudaEventCreateWithFlags(&ev0, cudaEventDisableTiming);
        cudaEventCreateWithFlags(&evR, cudaEventDisableTiming);
        cudaEventCreateWithFlags(&evS, cudaEventDisableTiming);
        init = true;
    }

    const size_t xn4 = (size_t)T_TOK * HDIM / 4;
    const size_t wn4 = (size_t)NEXP * WSZ / 4;
    const size_t sn4 = WSZ / 4;

    // fork side streams from the (captured) default stream
    cudaEventRecord(ev0, 0);
    cudaStreamWaitEvent(sR, ev0, 0);
    cudaStreamWaitEvent(sS, ev0, 0);

    reset_kernel<<<1, 32, 0, sR>>>();
    router_kernel<<<T_TOK / 4, 256, 0, sR>>>(x, rw, rb, logits);
    cudaEventRecord(evR, sR);

    {
        dim3 g(4096, 1, 2);
        split2<<<g, 256, 0, sS>>>(w2, p_w2, wn4,
                                  sw2, p_w2 + NEXP * WSZ, sn4);
    }
    zero_out<<<2048, 256, 0, sS>>>((float4*)out,
                                   (size_t)T_TOK * HDIM / 4);
    cudaEventRecord(evS, sS);

    {
        dim3 g(3072, 1, 5);
        split5<<<g, 256>>>(x,  p_x,  xn4,
                           w1, p_w1, wn4,
                           w3, p_w3, wn4,
                           sw1, p_w1 + NEXP * WSZ, sn4,
                           sw3, p_w3 + NEXP * WSZ, sn4);
    }

    cudaStreamWaitEvent(0, evR, 0);   // router/reset done before gemm13
    dim3 g13(FDIM / 128, T_TOK / 128, 9);
    gemm13_kernel<<<g13, 512, SMEMB>>>();

    cudaStreamWaitEvent(0, evS, 0);   // w2 split + zero done before gemm2
    dim3 g2(HDIM / 256, T_TOK / 128, 9);
    gemm2_kernel<<<g2, 512, SMEMB>>>(out);
}